// round 7
// baseline (speedup 1.0000x reference)
#include <cuda_runtime.h>
#include <cuda_fp16.h>
#include <cstdint>

#define N_TOK 32768
#define DIMX  1024
#define HID   2816
#define BK    64                    // halves per k-tile (128B data per row)
#define STAGES 3
#define ROWPITCH 144                // 128B data + 16B pad -> conflict-free ldmatrix
#define BM    256                   // A rows per CTA
#define BROWS 128                   // B rows per CTA
#define A_BYTES (BM * ROWPITCH)     // 36864
#define B_BYTES (BROWS * ROWPITCH)  // 18432
#define STAGE_BYTES (A_BYTES + B_BYTES)   // 55296
#define DYN_SMEM (STAGES * STAGE_BYTES)   // 165888

// ---------------- device scratch (no allocations allowed) -------------------
__device__ int    g_count[2];
__device__ int    g_slot[N_TOK];                     // token -> slot
__device__ int    g_word_mode;
__device__ __half g_xh[(size_t)2 * N_TOK * DIMX];    // gathered x, fp16
__device__ __half g_h [(size_t)2 * N_TOK * HID];     // silu(xW1^T)*(xW3^T), fp16
__device__ float  g_o [(size_t)2 * N_TOK * DIMX];    // h W2^T, fp32
__device__ __half g_w1h[(size_t)2 * HID * DIMX];
__device__ __half g_w3h[(size_t)2 * HID * DIMX];
__device__ __half g_w2h[(size_t)2 * DIMX * HID];

// ---------------- PTX helpers ------------------------------------------------
__device__ __forceinline__ uint32_t smem_u32(const void* p) {
    uint32_t a;
    asm("{ .reg .u64 t; cvta.to.shared.u64 t, %1; cvt.u32.u64 %0, t; }" : "=r"(a) : "l"(p));
    return a;
}
__device__ __forceinline__ void cp16s(uint32_t dst, const void* src) {
    asm volatile("cp.async.cg.shared.global [%0], [%1], 16;" :: "r"(dst), "l"(src));
}
__device__ __forceinline__ void ldmx4(uint32_t* r, uint32_t addr) {
    asm volatile("ldmatrix.sync.aligned.m8n8.x4.shared.b16 {%0,%1,%2,%3}, [%4];"
                 : "=r"(r[0]), "=r"(r[1]), "=r"(r[2]), "=r"(r[3]) : "r"(addr));
}
__device__ __forceinline__ void mma16816(float* c, const uint32_t* a, const uint32_t* b) {
    asm volatile(
        "mma.sync.aligned.m16n8k16.row.col.f32.f16.f16.f32 "
        "{%0,%1,%2,%3}, {%4,%5,%6,%7}, {%8,%9}, {%0,%1,%2,%3};"
        : "+f"(c[0]), "+f"(c[1]), "+f"(c[2]), "+f"(c[3])
        : "r"(a[0]), "r"(a[1]), "r"(a[2]), "r"(a[3]), "r"(b[0]), "r"(b[1]));
}
__device__ __forceinline__ float silu_f(float x) { return x / (1.0f + __expf(-x)); }

// ---------------- small kernels ----------------------------------------------
__global__ void reset_kernel() {
    if (threadIdx.x == 0) { g_count[0] = 0; g_count[1] = 0; g_word_mode = 1; }
}
__global__ void detect_kernel(const unsigned int* __restrict__ m) {
    int i = blockIdx.x * blockDim.x + threadIdx.x;   // 16384 threads = 64KB, in-bounds either way
    unsigned v = m[i];
    if (v != 0u && v != 1u && v != 0x3F800000u) g_word_mode = 0;
}
__global__ void route_kernel(const void* __restrict__ masks) {
    int n = blockIdx.x * blockDim.x + threadIdx.x;
    if (n >= N_TOK) return;
    bool m0;
    if (g_word_mode) m0 = ((const unsigned int*)masks)[n] != 0u;
    else             m0 = ((const unsigned char*)masks)[n] != 0;
    int e = m0 ? 0 : 1;                        // modality 0 wins on overlap
    int s = atomicAdd(&g_count[e], 1);
    g_slot[n] = e * N_TOK + s;
}
__global__ void gather_cvt(const float* __restrict__ x) {
    int t = blockIdx.x;
    int slot = g_slot[t];
    float4 v = ((const float4*)(x + (size_t)t * DIMX))[threadIdx.x];   // 256 thr * 4
    __half2 h0 = __floats2half2_rn(v.x, v.y);
    __half2 h1 = __floats2half2_rn(v.z, v.w);
    uint2 o = { *(uint32_t*)&h0, *(uint32_t*)&h1 };
    ((uint2*)(g_xh + (size_t)slot * DIMX))[threadIdx.x] = o;
}
__global__ void cvtw_all(const float4* __restrict__ w1, const float4* __restrict__ w3,
                         const float4* __restrict__ w2,
                         uint2* __restrict__ d1, uint2* __restrict__ d3,
                         uint2* __restrict__ d2, int n4) {
    int stride = gridDim.x * blockDim.x;
    for (int i = blockIdx.x * blockDim.x + threadIdx.x; i < 3 * n4; i += stride) {
        const float4* s; uint2* d; int j;
        if (i < n4)          { s = w1; d = d1; j = i; }
        else if (i < 2 * n4) { s = w3; d = d3; j = i - n4; }
        else                 { s = w2; d = d2; j = i - 2 * n4; }
        float4 v = s[j];
        __half2 h0 = __floats2half2_rn(v.x, v.y);
        __half2 h1 = __floats2half2_rn(v.z, v.w);
        d[j] = make_uint2(*(uint32_t*)&h0, *(uint32_t*)&h1);
    }
}

// ---------------- fp16 tensor-core GEMM ---------------------------------------
// BM=256 rows of A per CTA, 512 threads (16 warps: wr = wid&7 over M, wc = wid>>3 over N).
// DUAL : B = [w1 tile (64 rows) | w3 tile (64 rows)]; warp tile 32x32 per side;
//        epilogue silu(d1)*d3 -> fp16 C.   NTILE = 64 (cols per side).
// !DUAL: B = 128-row weight tile; warp tile 32x64; fp32 C.  NTILE = 128.
// Pipeline: 3 stages x BK=64, ONE __syncthreads per k-tile.
template <bool DUAL, int K, int NC, int NTILE>
__global__ void __launch_bounds__(512, 1)
gemm_fp16(const __half* __restrict__ A,
          const __half* __restrict__ W1,
          const __half* __restrict__ W3,
          void* __restrict__ Cout)
{
    extern __shared__ char dyn[];
    const int tid = threadIdx.x;
    const int wid = tid >> 5;
    const int l   = tid & 31;
    const int r0  = blockIdx.y * BM;
    const int e   = r0 >> 15;
    if ((r0 & (N_TOK - 1)) >= g_count[e]) return;
    const int cb  = blockIdx.x * NTILE;

    const uint32_t smem = smem_u32(dyn);
    const __half* W1e = W1 + (size_t)e * NC * K;
    const __half* W3e = DUAL ? (W3 + (size_t)e * NC * K) : W1e;

    // ---- cp.async descriptors: 3072 16B-chunks per stage, 6 per thread ----
    const __half* src[6];
    uint32_t off[6];
#pragma unroll
    for (int i = 0; i < 6; i++) {
        int id = tid + i * 512;
        if (id < 2048) {                      // A: 256 rows x 8 chunks
            int row = id >> 3, c = id & 7;
            src[i] = A + (size_t)(r0 + row) * K + c * 8;
            off[i] = row * ROWPITCH + c * 16;
        } else {                              // B: 128 rows x 8 chunks
            id -= 2048;
            int brow = id >> 3, c = id & 7;
            const __half* p;
            if (DUAL) p = (brow < 64) ? (W1e + (size_t)(cb + brow) * K)
                                      : (W3e + (size_t)(cb + brow - 64) * K);
            else      p = W1e + (size_t)(cb + brow) * K;
            src[i] = p + c * 8;
            off[i] = A_BYTES + brow * ROWPITCH + c * 16;
        }
    }

    // ---- ldmatrix lane offsets (constant across k) ----
    const int wr = wid & 7, wc = wid >> 3;
    constexpr int NW = DUAL ? 32 : 64;        // warp col span per side
    constexpr int NG = DUAL ? 2 : 4;          // ldmatrix.x4 groups per side
    uint32_t a_off[2];
#pragma unroll
    for (int mi = 0; mi < 2; mi++)
        a_off[mi] = (wr * 32 + mi * 16 + (l & 15)) * ROWPITCH + (l >> 4) * 16;
    uint32_t b_off[NG];
#pragma unroll
    for (int ng = 0; ng < NG; ng++)
        b_off[ng] = A_BYTES
                  + (wc * NW + ng * 16 + (l & 7) + ((l >> 4) << 3)) * ROWPITCH
                  + ((l >> 3) & 1) * 16;

    float acc[2][8][4];
#pragma unroll
    for (int mi = 0; mi < 2; mi++)
#pragma unroll
        for (int ni = 0; ni < 8; ni++)
#pragma unroll
            for (int q = 0; q < 4; q++) acc[mi][ni][q] = 0.f;

    const int KT = K / BK;
    // prologue: fill STAGES-1 stages
#pragma unroll
    for (int s = 0; s < STAGES - 1; s++) {
#pragma unroll
        for (int i = 0; i < 6; i++)
            cp16s(smem + s * STAGE_BYTES + off[i], src[i] + s * BK);
        asm volatile("cp.async.commit_group;");
    }

    for (int kt = 0; kt < KT; kt++) {
        // stage kt is complete once <= STAGES-2 groups remain outstanding
        asm volatile("cp.async.wait_group %0;" :: "n"(STAGES - 2));
        __syncthreads();   // also separates compute(kt-1) from overwrite below

        // issue loads for stage kt+STAGES-1 into slot (kt+STAGES-1) % STAGES
        if (kt + STAGES - 1 < KT) {
            const uint32_t dst = smem + ((kt + STAGES - 1) % STAGES) * STAGE_BYTES;
#pragma unroll
            for (int i = 0; i < 6; i++)
                cp16s(dst + off[i], src[i] + (kt + STAGES - 1) * BK);
        }
        asm volatile("cp.async.commit_group;");   // uniform group count

        const uint32_t st = smem + (kt % STAGES) * STAGE_BYTES;
#pragma unroll
        for (int kk = 0; kk < 4; kk++) {
            uint32_t a[2][4];
#pragma unroll
            for (int mi = 0; mi < 2; mi++) ldmx4(a[mi], st + a_off[mi] + kk * 32);

            if (DUAL) {
                uint32_t b1[2][4], b3[2][4];
#pragma unroll
                for (int ng = 0; ng < 2; ng++) {
                    ldmx4(b1[ng], st + b_off[ng] + kk * 32);
                    ldmx4(b3[ng], st + 64 * ROWPITCH + b_off[ng] + kk * 32);
                }
#pragma unroll
                for (int ni = 0; ni < 4; ni++) {
                    const uint32_t* f1 = &b1[ni >> 1][(ni & 1) * 2];
                    const uint32_t* f3 = &b3[ni >> 1][(ni & 1) * 2];
#pragma unroll
                    for (int mi = 0; mi < 2; mi++) {
                        mma16816(acc[mi][ni],     a[mi], f1);
                        mma16816(acc[mi][ni + 4], a[mi], f3);
                    }
                }
            } else {
                uint32_t b[4][4];
#pragma unroll
                for (int ng = 0; ng < 4; ng++) ldmx4(b[ng], st + b_off[ng] + kk * 32);
#pragma unroll
                for (int ni = 0; ni < 8; ni++) {
                    const uint32_t* f = &b[ni >> 1][(ni & 1) * 2];
#pragma unroll
                    for (int mi = 0; mi < 2; mi++) mma16816(acc[mi][ni], a[mi], f);
                }
            }
        }
    }

    // ---- epilogue ----
    const int tgrp = l >> 2, tq = l & 3;
    if (DUAL) {
        __half* Ch = (__half*)Cout;
#pragma unroll
        for (int mi = 0; mi < 2; mi++) {
            int row0 = r0 + wr * 32 + mi * 16 + tgrp;
#pragma unroll
            for (int ni = 0; ni < 4; ni++) {
                int col = cb + wc * 32 + ni * 8 + 2 * tq;
                float v0 = silu_f(acc[mi][ni][0]) * acc[mi][ni + 4][0];
                float v1 = silu_f(acc[mi][ni][1]) * acc[mi][ni + 4][1];
                float v2 = silu_f(acc[mi][ni][2]) * acc[mi][ni + 4][2];
                float v3 = silu_f(acc[mi][ni][3]) * acc[mi][ni + 4][3];
                __half2 h01 = __floats2half2_rn(v0, v1);
                __half2 h23 = __floats2half2_rn(v2, v3);
                *(__half2*)(Ch + (size_t)row0 * NC + col)       = h01;
                *(__half2*)(Ch + (size_t)(row0 + 8) * NC + col) = h23;
            }
        }
    } else {
        float* Cf = (float*)Cout;
#pragma unroll
        for (int mi = 0; mi < 2; mi++) {
            int row0 = r0 + wr * 32 + mi * 16 + tgrp;
#pragma unroll
            for (int ni = 0; ni < 8; ni++) {
                int col = cb + wc * 64 + ni * 8 + 2 * tq;
                *(float2*)(Cf + (size_t)row0 * NC + col) =
                    make_float2(acc[mi][ni][0], acc[mi][ni][1]);
                *(float2*)(Cf + (size_t)(row0 + 8) * NC + col) =
                    make_float2(acc[mi][ni][2], acc[mi][ni][3]);
            }
        }
    }
}

// ---------------- RMSNorm + scale + scatter ---------------------------------
__global__ void rms_scatter(const float* __restrict__ o,
                            const float* __restrict__ norm_w,
                            float* __restrict__ out)
{
    int t = blockIdx.x;
    int slot = g_slot[t];
    int e = slot >> 15;
    int tid = threadIdx.x;

    const float4* orow = (const float4*)(o + (size_t)slot * DIMX);
    float4 v0 = orow[tid], v1 = orow[tid + 128];
    float ss = v0.x*v0.x + v0.y*v0.y + v0.z*v0.z + v0.w*v0.w
             + v1.x*v1.x + v1.y*v1.y + v1.z*v1.z + v1.w*v1.w;
#pragma unroll
    for (int ofs = 16; ofs; ofs >>= 1) ss += __shfl_xor_sync(0xffffffffu, ss, ofs);
    __shared__ float wss[4];
    if ((tid & 31) == 0) wss[tid >> 5] = ss;
    __syncthreads();
    float r = rsqrtf((wss[0] + wss[1] + wss[2] + wss[3]) * (1.0f / DIMX) + 1e-5f);

    const float4* g = (const float4*)(norm_w + (size_t)e * DIMX);
    float4 g0 = g[tid], g1 = g[tid + 128];
    float4* dst = (float4*)(out + (size_t)t * DIMX);
    dst[tid]       = make_float4(v0.x*r*g0.x, v0.y*r*g0.y, v0.z*r*g0.z, v0.w*r*g0.w);
    dst[tid + 128] = make_float4(v1.x*r*g1.x, v1.y*r*g1.y, v1.z*r*g1.z, v1.w*r*g1.w);
}

// ---------------- launcher ----------------------------------------------------
extern "C" void kernel_launch(void* const* d_in, const int* in_sizes, int n_in,
                              void* d_out, int out_size)
{
    const float* x     = (const float*)d_in[0];
    const void*  masks = d_in[1];
    const float* w1    = (const float*)d_in[2];
    const float* w3    = (const float*)d_in[3];
    const float* w2    = (const float*)d_in[4];
    const float* nw    = (const float*)d_in[5];
    float* out = (float*)d_out;

    cudaFuncSetAttribute(gemm_fp16<true,  DIMX, HID,  64>,
                         cudaFuncAttributeMaxDynamicSharedMemorySize, DYN_SMEM);
    cudaFuncSetAttribute(gemm_fp16<false, HID,  DIMX, 128>,
                         cudaFuncAttributeMaxDynamicSharedMemorySize, DYN_SMEM);

    void *xh, *hp, *op, *w1h, *w3h, *w2h;
    cudaGetSymbolAddress(&xh,  g_xh);
    cudaGetSymbolAddress(&hp,  g_h);
    cudaGetSymbolAddress(&op,  g_o);
    cudaGetSymbolAddress(&w1h, g_w1h);
    cudaGetSymbolAddress(&w3h, g_w3h);
    cudaGetSymbolAddress(&w2h, g_w2h);

    reset_kernel<<<1, 32>>>();                                   // 0
    detect_kernel<<<64, 256>>>((const unsigned int*)masks);      // 1
    route_kernel<<<128, 256>>>(masks);                           // 2
    gather_cvt<<<N_TOK, 256>>>(x);                               // 3

    const int n4 = 2 * HID * DIMX / 4;
    cvtw_all<<<1024, 256>>>((const float4*)w1, (const float4*)w3, (const float4*)w2,
                            (uint2*)w1h, (uint2*)w3h, (uint2*)w2h, n4);  // 4

    // GEMM1: [2N,1024] x w1/w3 -> fused SwiGLU -> g_h [2N, HID] fp16       // 5
    gemm_fp16<true, DIMX, HID, 64><<<dim3(HID / 64, 2 * N_TOK / BM), 512, DYN_SMEM>>>(
        (const __half*)xh, (const __half*)w1h, (const __half*)w3h, hp);
    // GEMM2: [2N,2816] x w2 -> g_o [2N, DIM] fp32                          // 6
    gemm_fp16<false, HID, DIMX, 128><<<dim3(DIMX / 128, 2 * N_TOK / BM), 512, DYN_SMEM>>>(
        (const __half*)hp, (const __half*)w2h, (const __half*)w2h, op);

    rms_scatter<<<N_TOK, 128>>>((const float*)op, nw, out);                 // 7
}

// round 8
// speedup vs baseline: 1.0701x; 1.0701x over previous
#include <cuda_runtime.h>
#include <cuda_fp16.h>
#include <cstdint>

#define N_TOK 32768
#define DIMX  1024
#define HID   2816
#define BK    64                    // halves per k-tile (128B data per row)
#define STAGES 3
#define ROWPITCH 144                // 128B data + 16B pad -> conflict-free ldmatrix
#define A_BYTES (128 * ROWPITCH)    // 18432
#define STAGE_BYTES (2 * A_BYTES)   // A(128 rows) + B(128 rows) = 36864
#define DYN_SMEM (STAGES * STAGE_BYTES)   // 110592

// ---------------- device scratch (no allocations allowed) -------------------
__device__ int    g_count[2];                        // zeroed by detect_kernel
__device__ int    g_slot[N_TOK];                     // token -> slot
__device__ int    g_word_mode = 1;                   // re-armed by rms_scatter
__device__ __half g_xh[(size_t)2 * N_TOK * DIMX];    // gathered x, fp16
__device__ __half g_h [(size_t)2 * N_TOK * HID];     // silu(xW1^T)*(xW3^T), fp16
__device__ float  g_o [(size_t)2 * N_TOK * DIMX];    // h W2^T, fp32
__device__ __half g_w1h[(size_t)2 * HID * DIMX];
__device__ __half g_w3h[(size_t)2 * HID * DIMX];
__device__ __half g_w2h[(size_t)2 * DIMX * HID];

// ---------------- PTX helpers ------------------------------------------------
__device__ __forceinline__ uint32_t smem_u32(const void* p) {
    uint32_t a;
    asm("{ .reg .u64 t; cvta.to.shared.u64 t, %1; cvt.u32.u64 %0, t; }" : "=r"(a) : "l"(p));
    return a;
}
__device__ __forceinline__ void cp16s(uint32_t dst, const void* src) {
    asm volatile("cp.async.cg.shared.global [%0], [%1], 16;" :: "r"(dst), "l"(src));
}
__device__ __forceinline__ void ldmx4(uint32_t* r, uint32_t addr) {
    asm volatile("ldmatrix.sync.aligned.m8n8.x4.shared.b16 {%0,%1,%2,%3}, [%4];"
                 : "=r"(r[0]), "=r"(r[1]), "=r"(r[2]), "=r"(r[3]) : "r"(addr));
}
__device__ __forceinline__ void mma16816(float* c, const uint32_t* a, const uint32_t* b) {
    asm volatile(
        "mma.sync.aligned.m16n8k16.row.col.f32.f16.f16.f32 "
        "{%0,%1,%2,%3}, {%4,%5,%6,%7}, {%8,%9}, {%0,%1,%2,%3};"
        : "+f"(c[0]), "+f"(c[1]), "+f"(c[2]), "+f"(c[3])
        : "r"(a[0]), "r"(a[1]), "r"(a[2]), "r"(a[3]), "r"(b[0]), "r"(b[1]));
}
__device__ __forceinline__ float silu_f(float x) { return x / (1.0f + __expf(-x)); }

// ---------------- small kernels ----------------------------------------------
// launch 0: detect mask dtype AND zero the routing counters
__global__ void detect_kernel(const unsigned int* __restrict__ m) {
    int i = blockIdx.x * blockDim.x + threadIdx.x;   // 16384 threads = 64KB, in-bounds either way
    if (i == 0) { g_count[0] = 0; g_count[1] = 0; }
    unsigned v = m[i];
    if (v != 0u && v != 1u && v != 0x3F800000u) g_word_mode = 0;
}
// launch 1: route token -> slot and gather+convert its row in one kernel
__global__ void route_gather(const void* __restrict__ masks, const float* __restrict__ x) {
    int t = blockIdx.x;
    __shared__ int s_slot;
    if (threadIdx.x == 0) {
        bool m0;
        if (g_word_mode) m0 = ((const unsigned int*)masks)[t] != 0u;
        else             m0 = ((const unsigned char*)masks)[t] != 0;
        int e = m0 ? 0 : 1;                    // modality 0 wins on overlap
        int s = atomicAdd(&g_count[e], 1);
        int slot = e * N_TOK + s;
        g_slot[t] = slot;
        s_slot = slot;
    }
    __syncthreads();
    int slot = s_slot;
    float4 v = ((const float4*)(x + (size_t)t * DIMX))[threadIdx.x];   // 256 thr * 4
    __half2 h0 = __floats2half2_rn(v.x, v.y);
    __half2 h1 = __floats2half2_rn(v.z, v.w);
    ((uint2*)(g_xh + (size_t)slot * DIMX))[threadIdx.x] =
        make_uint2(*(uint32_t*)&h0, *(uint32_t*)&h1);
}
// launch 2: convert all three weight tensors
__global__ void cvtw_all(const float4* __restrict__ w1, const float4* __restrict__ w3,
                         const float4* __restrict__ w2,
                         uint2* __restrict__ d1, uint2* __restrict__ d3,
                         uint2* __restrict__ d2, int n4) {
    int stride = gridDim.x * blockDim.x;
    for (int i = blockIdx.x * blockDim.x + threadIdx.x; i < 3 * n4; i += stride) {
        const float4* s; uint2* d; int j;
        if (i < n4)          { s = w1; d = d1; j = i; }
        else if (i < 2 * n4) { s = w3; d = d3; j = i - n4; }
        else                 { s = w2; d = d2; j = i - 2 * n4; }
        float4 v = s[j];
        __half2 h0 = __floats2half2_rn(v.x, v.y);
        __half2 h1 = __floats2half2_rn(v.z, v.w);
        d[j] = make_uint2(*(uint32_t*)&h0, *(uint32_t*)&h1);
    }
}

// ---------------- fp16 tensor-core GEMM (R6 proven config) --------------------
// BM=128 rows of A per CTA. 8 warps: wr = wid&3 over M (32 rows), wc = wid>>2 over N.
// DUAL : B = [w1 tile (64 rows) | w3 tile (64 rows)]; warp tile 32x32 per side;
//        epilogue silu(d1)*d3 -> fp16 C.   NTILE = 64 (cols per side).
// !DUAL: B = 128-row weight tile; warp tile 32x64; fp32 C.  NTILE = 128.
// Pipeline: 3 stages x BK=64, ONE __syncthreads per k-tile.
template <bool DUAL, int K, int NC, int NTILE>
__global__ void __launch_bounds__(256, 2)
gemm_fp16(const __half* __restrict__ A,
          const __half* __restrict__ W1,
          const __half* __restrict__ W3,
          void* __restrict__ Cout)
{
    extern __shared__ char dyn[];
    const int tid = threadIdx.x;
    const int wid = tid >> 5;
    const int l   = tid & 31;
    const int r0  = blockIdx.y * 128;
    const int e   = r0 >> 15;
    if ((r0 & (N_TOK - 1)) >= g_count[e]) return;
    const int cb  = blockIdx.x * NTILE;

    const uint32_t smem = smem_u32(dyn);
    const __half* W1e = W1 + (size_t)e * NC * K;
    const __half* W3e = DUAL ? (W3 + (size_t)e * NC * K) : W1e;

    // ---- cp.async descriptors: 2048 16B-chunks per stage, 8 per thread ----
    const __half* src[8];
    uint32_t off[8];
#pragma unroll
    for (int i = 0; i < 8; i++) {
        int id = tid + i * 256;
        if (id < 1024) {                      // A: 128 rows x 8 chunks
            int row = id >> 3, c = id & 7;
            src[i] = A + (size_t)(r0 + row) * K + c * 8;
            off[i] = row * ROWPITCH + c * 16;
        } else {                              // B: 128 rows x 8 chunks
            id -= 1024;
            int brow = id >> 3, c = id & 7;
            const __half* p;
            if (DUAL) p = (brow < 64) ? (W1e + (size_t)(cb + brow) * K)
                                      : (W3e + (size_t)(cb + brow - 64) * K);
            else      p = W1e + (size_t)(cb + brow) * K;
            src[i] = p + c * 8;
            off[i] = A_BYTES + brow * ROWPITCH + c * 16;
        }
    }

    // ---- ldmatrix lane offsets (constant across k) ----
    const int wr = wid & 3, wc = wid >> 2;
    constexpr int NW = DUAL ? 32 : 64;        // warp col span per side
    constexpr int NG = DUAL ? 2 : 4;          // ldmatrix.x4 groups per side
    uint32_t a_off[2];
#pragma unroll
    for (int mi = 0; mi < 2; mi++)
        a_off[mi] = (wr * 32 + mi * 16 + (l & 15)) * ROWPITCH + (l >> 4) * 16;
    uint32_t b_off[NG];
#pragma unroll
    for (int ng = 0; ng < NG; ng++)
        b_off[ng] = A_BYTES
                  + (wc * NW + ng * 16 + (l & 7) + ((l >> 4) << 3)) * ROWPITCH
                  + ((l >> 3) & 1) * 16;

    float acc[2][8][4];
#pragma unroll
    for (int mi = 0; mi < 2; mi++)
#pragma unroll
        for (int ni = 0; ni < 8; ni++)
#pragma unroll
            for (int q = 0; q < 4; q++) acc[mi][ni][q] = 0.f;

    const int KT = K / BK;
    // prologue: fill STAGES-1 stages
#pragma unroll
    for (int s = 0; s < STAGES - 1; s++) {
#pragma unroll
        for (int i = 0; i < 8; i++)
            cp16s(smem + s * STAGE_BYTES + off[i], src[i] + s * BK);
        asm volatile("cp.async.commit_group;");
    }

    for (int kt = 0; kt < KT; kt++) {
        asm volatile("cp.async.wait_group %0;" :: "n"(STAGES - 2));
        __syncthreads();

        if (kt + STAGES - 1 < KT) {
            const uint32_t dst = smem + ((kt + STAGES - 1) % STAGES) * STAGE_BYTES;
#pragma unroll
            for (int i = 0; i < 8; i++)
                cp16s(dst + off[i], src[i] + (kt + STAGES - 1) * BK);
        }
        asm volatile("cp.async.commit_group;");   // uniform group count

        const uint32_t st = smem + (kt % STAGES) * STAGE_BYTES;
#pragma unroll
        for (int kk = 0; kk < 4; kk++) {
            uint32_t a[2][4];
#pragma unroll
            for (int mi = 0; mi < 2; mi++) ldmx4(a[mi], st + a_off[mi] + kk * 32);

            if (DUAL) {
                uint32_t b1[2][4], b3[2][4];
#pragma unroll
                for (int ng = 0; ng < 2; ng++) {
                    ldmx4(b1[ng], st + b_off[ng] + kk * 32);
                    ldmx4(b3[ng], st + 64 * ROWPITCH + b_off[ng] + kk * 32);
                }
#pragma unroll
                for (int ni = 0; ni < 4; ni++) {
                    const uint32_t* f1 = &b1[ni >> 1][(ni & 1) * 2];
                    const uint32_t* f3 = &b3[ni >> 1][(ni & 1) * 2];
#pragma unroll
                    for (int mi = 0; mi < 2; mi++) {
                        mma16816(acc[mi][ni],     a[mi], f1);
                        mma16816(acc[mi][ni + 4], a[mi], f3);
                    }
                }
            } else {
                uint32_t b[4][4];
#pragma unroll
                for (int ng = 0; ng < 4; ng++) ldmx4(b[ng], st + b_off[ng] + kk * 32);
#pragma unroll
                for (int ni = 0; ni < 8; ni++) {
                    const uint32_t* f = &b[ni >> 1][(ni & 1) * 2];
#pragma unroll
                    for (int mi = 0; mi < 2; mi++) mma16816(acc[mi][ni], a[mi], f);
                }
            }
        }
    }

    // ---- epilogue ----
    const int tgrp = l >> 2, tq = l & 3;
    if (DUAL) {
        __half* Ch = (__half*)Cout;
#pragma unroll
        for (int mi = 0; mi < 2; mi++) {
            int row0 = r0 + wr * 32 + mi * 16 + tgrp;
#pragma unroll
            for (int ni = 0; ni < 4; ni++) {
                int col = cb + wc * 32 + ni * 8 + 2 * tq;
                float v0 = silu_f(acc[mi][ni][0]) * acc[mi][ni + 4][0];
                float v1 = silu_f(acc[mi][ni][1]) * acc[mi][ni + 4][1];
                float v2 = silu_f(acc[mi][ni][2]) * acc[mi][ni + 4][2];
                float v3 = silu_f(acc[mi][ni][3]) * acc[mi][ni + 4][3];
                __half2 h01 = __floats2half2_rn(v0, v1);
                __half2 h23 = __floats2half2_rn(v2, v3);
                *(__half2*)(Ch + (size_t)row0 * NC + col)       = h01;
                *(__half2*)(Ch + (size_t)(row0 + 8) * NC + col) = h23;
            }
        }
    } else {
        float* Cf = (float*)Cout;
#pragma unroll
        for (int mi = 0; mi < 2; mi++) {
            int row0 = r0 + wr * 32 + mi * 16 + tgrp;
#pragma unroll
            for (int ni = 0; ni < 8; ni++) {
                int col = cb + wc * 64 + ni * 8 + 2 * tq;
                *(float2*)(Cf + (size_t)row0 * NC + col) =
                    make_float2(acc[mi][ni][0], acc[mi][ni][1]);
                *(float2*)(Cf + (size_t)(row0 + 8) * NC + col) =
                    make_float2(acc[mi][ni][2], acc[mi][ni][3]);
            }
        }
    }
}

// ---------------- RMSNorm + scale + scatter (also re-arms word_mode) ---------
__global__ void rms_scatter(const float* __restrict__ o,
                            const float* __restrict__ norm_w,
                            float* __restrict__ out)
{
    int t = blockIdx.x;
    int tid = threadIdx.x;
    if (t == 0 && tid == 0) g_word_mode = 1;   // re-arm for next call's detect
    int slot = g_slot[t];
    int e = slot >> 15;

    const float4* orow = (const float4*)(o + (size_t)slot * DIMX);
    float4 v0 = orow[tid], v1 = orow[tid + 128];
    float ss = v0.x*v0.x + v0.y*v0.y + v0.z*v0.z + v0.w*v0.w
             + v1.x*v1.x + v1.y*v1.y + v1.z*v1.z + v1.w*v1.w;
#pragma unroll
    for (int ofs = 16; ofs; ofs >>= 1) ss += __shfl_xor_sync(0xffffffffu, ss, ofs);
    __shared__ float wss[4];
    if ((tid & 31) == 0) wss[tid >> 5] = ss;
    __syncthreads();
    float r = rsqrtf((wss[0] + wss[1] + wss[2] + wss[3]) * (1.0f / DIMX) + 1e-5f);

    const float4* g = (const float4*)(norm_w + (size_t)e * DIMX);
    float4 g0 = g[tid], g1 = g[tid + 128];
    float4* dst = (float4*)(out + (size_t)t * DIMX);
    dst[tid]       = make_float4(v0.x*r*g0.x, v0.y*r*g0.y, v0.z*r*g0.z, v0.w*r*g0.w);
    dst[tid + 128] = make_float4(v1.x*r*g1.x, v1.y*r*g1.y, v1.z*r*g1.z, v1.w*r*g1.w);
}

// ---------------- launcher ----------------------------------------------------
extern "C" void kernel_launch(void* const* d_in, const int* in_sizes, int n_in,
                              void* d_out, int out_size)
{
    const float* x     = (const float*)d_in[0];
    const void*  masks = d_in[1];
    const float* w1    = (const float*)d_in[2];
    const float* w3    = (const float*)d_in[3];
    const float* w2    = (const float*)d_in[4];
    const float* nw    = (const float*)d_in[5];
    float* out = (float*)d_out;

    cudaFuncSetAttribute(gemm_fp16<true,  DIMX, HID,  64>,
                         cudaFuncAttributeMaxDynamicSharedMemorySize, DYN_SMEM);
    cudaFuncSetAttribute(gemm_fp16<false, HID,  DIMX, 128>,
                         cudaFuncAttributeMaxDynamicSharedMemorySize, DYN_SMEM);

    void *xh, *hp, *op, *w1h, *w3h, *w2h;
    cudaGetSymbolAddress(&xh,  g_xh);
    cudaGetSymbolAddress(&hp,  g_h);
    cudaGetSymbolAddress(&op,  g_o);
    cudaGetSymbolAddress(&w1h, g_w1h);
    cudaGetSymbolAddress(&w3h, g_w3h);
    cudaGetSymbolAddress(&w2h, g_w2h);

    detect_kernel<<<64, 256>>>((const unsigned int*)masks);            // 0
    route_gather<<<N_TOK, 256>>>(masks, x);                            // 1

    const int n4 = 2 * HID * DIMX / 4;
    cvtw_all<<<1024, 256>>>((const float4*)w1, (const float4*)w3, (const float4*)w2,
                            (uint2*)w1h, (uint2*)w3h, (uint2*)w2h, n4);        // 2

    // GEMM1: [2N,1024] x w1/w3 -> fused SwiGLU -> g_h [2N, HID] fp16          // 3
    gemm_fp16<true, DIMX, HID, 64><<<dim3(HID / 64, 2 * N_TOK / 128), 256, DYN_SMEM>>>(
        (const __half*)xh, (const __half*)w1h, (const __half*)w3h, hp);
    // GEMM2: [2N,2816] x w2 -> g_o [2N, DIM] fp32                             // 4
    gemm_fp16<false, HID, DIMX, 128><<<dim3(DIMX / 128, 2 * N_TOK / 128), 256, DYN_SMEM>>>(
        (const __half*)hp, (const __half*)w2h, (const __half*)w2h, op);

    rms_scatter<<<N_TOK, 128>>>((const float*)op, nw, out);                    // 5
}